// round 1
// baseline (speedup 1.0000x reference)
#include <cuda_runtime.h>
#include <math.h>

// ---------------- problem constants ----------------
#define D_MODEL  1024
#define NHEADS   16
#define HDIM     64
#define NTOK     2048
#define BATCH    2
#define MROWS    (BATCH*NTOK)       // 4096
#define QKVCOLS  (3*D_MODEL)        // 3072

// ---------------- scratch (device globals; no cudaMalloc allowed) ----------------
__device__ float g_qkv[3*BATCH*NHEADS*NTOK*HDIM]; // [which][B][H][N][D]
__device__ float g_att[MROWS*D_MODEL];            // [B*N][H*D]
__device__ float g_cos[NTOK*HDIM];
__device__ float g_sin[NTOK*HDIM];
__device__ float g_xs [NTOK*HDIM];

// ============================================================
// Kernel 1: xpos/ND-RoPE tables (fp64 math, matches numpy ref)
// ============================================================
__global__ void rope_tables_kernel() {
    int idx = blockIdx.x * blockDim.x + threadIdx.x;   // n*64 + d
    if (idx >= NTOK*HDIM) return;
    int n = idx >> 6;
    int d = idx & 63;
    int axis = d >> 5;        // 0: spatial axis of size 32, 1: size 64
    int jj   = d & 31;
    int p    = jj >> 1;       // pair index within axis, 0..15
    double t, half;
    if (axis == 0) { t = (double)(n >> 6); half = 16.0; }   // i0 = n / 64
    else           { t = (double)(n & 63); half = 32.0; }   // i1 = n % 64
    double inv_freq = pow(10000.0, -((double)(2*p)) / 32.0);
    double f  = t * inv_freq;
    double sbase = ((double)(2*p) + 0.4*32.0) / (1.4*32.0);
    double power = (t - half) / 64.0;                        // XPOS_SCALE_BASE = 64
    double sc = pow(sbase, power);
    g_cos[idx] = (float)cos(f);
    g_sin[idx] = (float)sin(f);
    g_xs [idx] = (float)sc;
}

// ============================================================
// Kernel 2: QKV GEMM  C[4096,3072] = X[4096,1024]*W[1024,1024*3] + b
//           epilogue scatters into g_qkv[which][B][H][N][D]
// ============================================================
__global__ __launch_bounds__(256) void gemm_qkv_kernel(
    const float* __restrict__ X, const float* __restrict__ W,
    const float* __restrict__ bias)
{
    __shared__ float As[16][132];   // [k][m], padded
    __shared__ float Bs[16][128];   // [k][n]
    const int K = D_MODEL, NC = QKVCOLS;
    int tid = threadIdx.x;
    int bm = blockIdx.y, bn = blockIdx.x;
    int m0 = (tid >> 4) << 3;
    int n0 = (tid & 15) << 3;
    float acc[8][8];
#pragma unroll
    for (int i = 0; i < 8; i++)
#pragma unroll
        for (int j = 0; j < 8; j++) acc[i][j] = 0.f;

    int ar  = tid >> 2;          // 0..63
    int ak  = (tid & 3) << 2;    // 0,4,8,12
    int bk  = tid >> 5;          // 0..7
    int bn4 = (tid & 31) << 2;   // 0..124
    const float* Xp = X + (size_t)(bm*128)*K;
    const float* Wp = W + bn*128;

    for (int k0 = 0; k0 < K; k0 += 16) {
        float4 a0 = *(const float4*)(Xp + (size_t)ar*K      + k0 + ak);
        float4 a1 = *(const float4*)(Xp + (size_t)(ar+64)*K + k0 + ak);
        float4 b0 = *(const float4*)(Wp + (size_t)(k0+bk  )*NC + bn4);
        float4 b1 = *(const float4*)(Wp + (size_t)(k0+bk+8)*NC + bn4);
        __syncthreads();
        As[ak+0][ar] = a0.x; As[ak+1][ar] = a0.y; As[ak+2][ar] = a0.z; As[ak+3][ar] = a0.w;
        As[ak+0][ar+64] = a1.x; As[ak+1][ar+64] = a1.y; As[ak+2][ar+64] = a1.z; As[ak+3][ar+64] = a1.w;
        *(float4*)&Bs[bk  ][bn4] = b0;
        *(float4*)&Bs[bk+8][bn4] = b1;
        __syncthreads();
#pragma unroll
        for (int k = 0; k < 16; k++) {
            float a[8], b[8];
            *(float4*)(a)   = *(const float4*)&As[k][m0];
            *(float4*)(a+4) = *(const float4*)&As[k][m0+4];
            *(float4*)(b)   = *(const float4*)&Bs[k][n0];
            *(float4*)(b+4) = *(const float4*)&Bs[k][n0+4];
#pragma unroll
            for (int i = 0; i < 8; i++)
#pragma unroll
                for (int j = 0; j < 8; j++) acc[i][j] += a[i]*b[j];
        }
    }

    // epilogue: bias + scatter to [which][B][H][N][D]
    int col0  = bn*128 + n0;                  // 8-wide strip stays in one head
    int which = col0 >> 10;
    int h     = (col0 & 1023) >> 6;
    int dd    = col0 & 63;
#pragma unroll
    for (int i = 0; i < 8; i++) {
        int gr = bm*128 + m0 + i;
        int b  = gr >> 11;
        int n  = gr & 2047;
        float* dst = g_qkv + ((size_t)(((which*BATCH)+b)*NHEADS + h)*NTOK + n)*HDIM + dd;
        float4 v0 = make_float4(acc[i][0]+bias[col0+0], acc[i][1]+bias[col0+1],
                                acc[i][2]+bias[col0+2], acc[i][3]+bias[col0+3]);
        float4 v1 = make_float4(acc[i][4]+bias[col0+4], acc[i][5]+bias[col0+5],
                                acc[i][6]+bias[col0+6], acc[i][7]+bias[col0+7]);
        *(float4*)(dst)   = v0;
        *(float4*)(dst+4) = v1;
    }
}

// ============================================================
// Kernel 3: RoPE apply (q * xs, k / xs), one thread per pair
// ============================================================
__global__ void rope_apply_kernel() {
    int idx = blockIdx.x * blockDim.x + threadIdx.x;  // < 2*2*16*2048*32 = 4194304
    int pr = idx & 31;
    int n  = (idx >> 5)  & 2047;
    int h  = (idx >> 16) & 15;
    int b  = (idx >> 20) & 1;
    int w  = (idx >> 21) & 1;      // 0 = q, 1 = k
    size_t base = ((size_t)((w*BATCH+b)*NHEADS + h)*NTOK + n)*HDIM + (pr << 1);
    float x0 = g_qkv[base], x1 = g_qkv[base+1];
    int ti = (n << 6) + (pr << 1);
    float c = g_cos[ti], s = g_sin[ti], xs = g_xs[ti];
    float y0 = x0*c - x1*s;
    float y1 = x1*c + x0*s;
    if (w == 0) { y0 *= xs; y1 *= xs; }
    else        { y0 /= xs; y1 /= xs; }
    g_qkv[base]   = y0;
    g_qkv[base+1] = y1;
}

// ============================================================
// Kernel 4: fused flash attention (fp32, online softmax)
//   grid (16, 32): q-tile x (b*h).  128 q-rows/CTA, 64 kv/iter.
// ============================================================
#define FBM 128
#define FBN 64
#define QS_ST 68
#define KS_ST 68
#define FLASH_SMEM ((FBM*QS_ST + FBN*KS_ST + FBN*HDIM + FBM*QS_ST) * 4)

__global__ __launch_bounds__(256, 2) void flash_kernel() {
    extern __shared__ float smem[];
    float* Qs = smem;                       // [128][68] (pre-scaled by 1/8)
    float* Ks = Qs + FBM*QS_ST;             // [64][68]
    float* Vs = Ks + FBN*KS_ST;             // [64][64]
    float* Ps = Vs + FBN*HDIM;              // [128][68]

    int tid = threadIdx.x;
    int qt = blockIdx.x;
    int bh = blockIdx.y;
    int b = bh >> 4, h = bh & 15;
    int rg = tid >> 4, cg = tid & 15;
    int r0 = rg << 3;      // 8 rows
    int c0 = cg << 2;      // 4 cols (kv / head-dim)

    const float* Qg = g_qkv + ((size_t)((0*BATCH+b)*NHEADS + h))*NTOK*HDIM + (size_t)qt*FBM*HDIM;
    const float* Kg = g_qkv + ((size_t)((1*BATCH+b)*NHEADS + h))*NTOK*HDIM;
    const float* Vg = g_qkv + ((size_t)((2*BATCH+b)*NHEADS + h))*NTOK*HDIM;

    // load Q tile (scaled by head_dim^-0.5 = 0.125)
    for (int i = tid; i < FBM*HDIM/4; i += 256) {
        int r = i >> 4, c4 = (i & 15) << 2;
        float4 v = *(const float4*)(Qg + r*HDIM + c4);
        float* q = &Qs[r*QS_ST + c4];
        q[0] = v.x*0.125f; q[1] = v.y*0.125f; q[2] = v.z*0.125f; q[3] = v.w*0.125f;
    }

    float o[8][4];
    float m[8], l[8];
#pragma unroll
    for (int i = 0; i < 8; i++) {
        m[i] = -1e30f; l[i] = 0.f;
#pragma unroll
        for (int j = 0; j < 4; j++) o[i][j] = 0.f;
    }

    for (int kt = 0; kt < NTOK/FBN; kt++) {
        __syncthreads();   // protect prior-iter reads of Ks/Vs/Ps
        for (int i = tid; i < FBN*HDIM/4; i += 256) {
            int r = i >> 4, c4 = (i & 15) << 2;
            float4 kv = *(const float4*)(Kg + (size_t)kt*FBN*HDIM + r*HDIM + c4);
            float* kk = &Ks[r*KS_ST + c4];
            kk[0] = kv.x; kk[1] = kv.y; kk[2] = kv.z; kk[3] = kv.w;
            float4 vv = *(const float4*)(Vg + (size_t)kt*FBN*HDIM + r*HDIM + c4);
            *(float4*)&Vs[r*HDIM + c4] = vv;
        }
        __syncthreads();

        // ---- S = Q K^T (scaled) ----
        float s[8][4];
#pragma unroll
        for (int i = 0; i < 8; i++)
#pragma unroll
            for (int j = 0; j < 4; j++) s[i][j] = 0.f;

#pragma unroll 4
        for (int k4 = 0; k4 < HDIM; k4 += 4) {
            float4 kb[4];
#pragma unroll
            for (int j = 0; j < 4; j++)
                kb[j] = *(const float4*)&Ks[(c0+j)*KS_ST + k4];
#pragma unroll
            for (int i = 0; i < 8; i++) {
                float4 qa = *(const float4*)&Qs[(r0+i)*QS_ST + k4];
#pragma unroll
                for (int j = 0; j < 4; j++)
                    s[i][j] += qa.x*kb[j].x + qa.y*kb[j].y + qa.z*kb[j].z + qa.w*kb[j].w;
            }
        }

        // ---- online softmax (row groups = 16 lanes, inside one warp half) ----
#pragma unroll
        for (int i = 0; i < 8; i++) {
            float tm = fmaxf(fmaxf(s[i][0], s[i][1]), fmaxf(s[i][2], s[i][3]));
            tm = fmaxf(tm, __shfl_xor_sync(0xffffffffu, tm, 1));
            tm = fmaxf(tm, __shfl_xor_sync(0xffffffffu, tm, 2));
            tm = fmaxf(tm, __shfl_xor_sync(0xffffffffu, tm, 4));
            tm = fmaxf(tm, __shfl_xor_sync(0xffffffffu, tm, 8));
            float mn   = fmaxf(m[i], tm);
            float corr = __expf(m[i] - mn);
            float rs = 0.f;
#pragma unroll
            for (int j = 0; j < 4; j++) {
                float p = __expf(s[i][j] - mn);
                s[i][j] = p;
                rs += p;
            }
            rs += __shfl_xor_sync(0xffffffffu, rs, 1);
            rs += __shfl_xor_sync(0xffffffffu, rs, 2);
            rs += __shfl_xor_sync(0xffffffffu, rs, 4);
            rs += __shfl_xor_sync(0xffffffffu, rs, 8);
            l[i] = l[i]*corr + rs;
            m[i] = mn;
#pragma unroll
            for (int j = 0; j < 4; j++) {
                o[i][j] *= corr;
                Ps[(r0+i)*QS_ST + c0 + j] = s[i][j];
            }
        }
        __syncthreads();

        // ---- O += P V ----
#pragma unroll 8
        for (int c = 0; c < FBN; c++) {
            float4 vv = *(const float4*)&Vs[c*HDIM + c0];
#pragma unroll
            for (int i = 0; i < 8; i++) {
                float p = Ps[(r0+i)*QS_ST + c];
                o[i][0] += p*vv.x; o[i][1] += p*vv.y;
                o[i][2] += p*vv.z; o[i][3] += p*vv.w;
            }
        }
    }

    // epilogue: normalize, write [B][N][H*D]
#pragma unroll
    for (int i = 0; i < 8; i++) {
        float inv = 1.f / l[i];
        int n = qt*FBM + r0 + i;
        float4 v = make_float4(o[i][0]*inv, o[i][1]*inv, o[i][2]*inv, o[i][3]*inv);
        *(float4*)&g_att[((size_t)(b*NTOK + n))*D_MODEL + h*HDIM + c0] = v;
    }
}

// ============================================================
// Kernel 5: proj GEMM  out[4096,1024] = g_att * w_proj + b_proj
// ============================================================
__global__ __launch_bounds__(256) void gemm_proj_kernel(
    const float* __restrict__ W, const float* __restrict__ bias,
    float* __restrict__ out)
{
    __shared__ float As[16][132];
    __shared__ float Bs[16][128];
    const int K = D_MODEL, NC = D_MODEL;
    int tid = threadIdx.x;
    int bm = blockIdx.y, bn = blockIdx.x;
    int m0 = (tid >> 4) << 3;
    int n0 = (tid & 15) << 3;
    float acc[8][8];
#pragma unroll
    for (int i = 0; i < 8; i++)
#pragma unroll
        for (int j = 0; j < 8; j++) acc[i][j] = 0.f;

    int ar  = tid >> 2;
    int ak  = (tid & 3) << 2;
    int bk  = tid >> 5;
    int bn4 = (tid & 31) << 2;
    const float* Xp = g_att + (size_t)(bm*128)*K;
    const float* Wp = W + bn*128;

    for (int k0 = 0; k0 < K; k0 += 16) {
        float4 a0 = *(const float4*)(Xp + (size_t)ar*K      + k0 + ak);
        float4 a1 = *(const float4*)(Xp + (size_t)(ar+64)*K + k0 + ak);
        float4 b0 = *(const float4*)(Wp + (size_t)(k0+bk  )*NC + bn4);
        float4 b1 = *(const float4*)(Wp + (size_t)(k0+bk+8)*NC + bn4);
        __syncthreads();
        As[ak+0][ar] = a0.x; As[ak+1][ar] = a0.y; As[ak+2][ar] = a0.z; As[ak+3][ar] = a0.w;
        As[ak+0][ar+64] = a1.x; As[ak+1][ar+64] = a1.y; As[ak+2][ar+64] = a1.z; As[ak+3][ar+64] = a1.w;
        *(float4*)&Bs[bk  ][bn4] = b0;
        *(float4*)&Bs[bk+8][bn4] = b1;
        __syncthreads();
#pragma unroll
        for (int k = 0; k < 16; k++) {
            float a[8], b[8];
            *(float4*)(a)   = *(const float4*)&As[k][m0];
            *(float4*)(a+4) = *(const float4*)&As[k][m0+4];
            *(float4*)(b)   = *(const float4*)&Bs[k][n0];
            *(float4*)(b+4) = *(const float4*)&Bs[k][n0+4];
#pragma unroll
            for (int i = 0; i < 8; i++)
#pragma unroll
                for (int j = 0; j < 8; j++) acc[i][j] += a[i]*b[j];
        }
    }

    int col0 = bn*128 + n0;
#pragma unroll
    for (int i = 0; i < 8; i++) {
        int gr = bm*128 + m0 + i;
        float4 v0 = make_float4(acc[i][0]+bias[col0+0], acc[i][1]+bias[col0+1],
                                acc[i][2]+bias[col0+2], acc[i][3]+bias[col0+3]);
        float4 v1 = make_float4(acc[i][4]+bias[col0+4], acc[i][5]+bias[col0+5],
                                acc[i][6]+bias[col0+6], acc[i][7]+bias[col0+7]);
        float* dst = out + (size_t)gr*NC + col0;
        *(float4*)(dst)   = v0;
        *(float4*)(dst+4) = v1;
    }
}

// ============================================================
// launch
// ============================================================
extern "C" void kernel_launch(void* const* d_in, const int* in_sizes, int n_in,
                              void* d_out, int out_size) {
    const float* x      = (const float*)d_in[0];
    const float* w_qkv  = (const float*)d_in[1];
    const float* b_qkv  = (const float*)d_in[2];
    const float* w_proj = (const float*)d_in[3];
    const float* b_proj = (const float*)d_in[4];
    float* out = (float*)d_out;

    (void)in_sizes; (void)n_in; (void)out_size;

    // 1. RoPE tables
    rope_tables_kernel<<<(NTOK*HDIM)/256, 256>>>();
    // 2. QKV projection (+ transpose into [which][B][H][N][D])
    gemm_qkv_kernel<<<dim3(QKVCOLS/128, MROWS/128), 256>>>(x, w_qkv, b_qkv);
    // 3. RoPE / xpos
    rope_apply_kernel<<<(2*BATCH*NHEADS*NTOK*(HDIM/2))/256, 256>>>();
    // 4. flash attention
    cudaFuncSetAttribute(flash_kernel, cudaFuncAttributeMaxDynamicSharedMemorySize, FLASH_SMEM);
    flash_kernel<<<dim3(NTOK/FBM, BATCH*NHEADS), 256, FLASH_SMEM>>>();
    // 5. output projection
    gemm_proj_kernel<<<dim3(D_MODEL/128, MROWS/128), 256>>>(w_proj, b_proj, out);
}

// round 2
// speedup vs baseline: 2.7694x; 2.7694x over previous
#include <cuda_runtime.h>
#include <math.h>

// ---------------- problem constants ----------------
#define D_MODEL  1024
#define NHEADS   16
#define HDIM     64
#define NTOK     2048
#define BATCH    2
#define MROWS    (BATCH*NTOK)       // 4096
#define QKVCOLS  (3*D_MODEL)        // 3072

// ---------------- scratch ----------------
__device__ float g_qkv[3*BATCH*NHEADS*NTOK*HDIM]; // [which][B][H][N][D]
__device__ float g_att[MROWS*D_MODEL];            // [B*N][H*D]
__device__ float g_cos[NTOK*HDIM];
__device__ float g_sin[NTOK*HDIM];
__device__ float g_xs [NTOK*HDIM];

// ---------------- tf32 helpers ----------------
__device__ __forceinline__ unsigned f2tf(float f) {
    unsigned u;
    asm("cvt.rna.tf32.f32 %0, %1;" : "=r"(u) : "f"(f));
    return u;
}
__device__ __forceinline__ void mma8(float c[4], const unsigned a[4], const unsigned b[2]) {
    asm("mma.sync.aligned.m16n8k8.row.col.f32.tf32.tf32.f32 "
        "{%0,%1,%2,%3},{%4,%5,%6,%7},{%8,%9},{%0,%1,%2,%3};"
        : "+f"(c[0]), "+f"(c[1]), "+f"(c[2]), "+f"(c[3])
        : "r"(a[0]), "r"(a[1]), "r"(a[2]), "r"(a[3]), "r"(b[0]), "r"(b[1]));
}

// ============================================================
// Kernel 1: xpos/ND-RoPE tables (fp64, matches numpy ref)
// ============================================================
__global__ void rope_tables_kernel() {
    int idx = blockIdx.x * blockDim.x + threadIdx.x;
    if (idx >= NTOK*HDIM) return;
    int n = idx >> 6;
    int d = idx & 63;
    int axis = d >> 5;
    int jj   = d & 31;
    int p    = jj >> 1;
    double t, half;
    if (axis == 0) { t = (double)(n >> 6); half = 16.0; }
    else           { t = (double)(n & 63); half = 32.0; }
    double inv_freq = pow(10000.0, -((double)(2*p)) / 32.0);
    double f  = t * inv_freq;
    double sbase = ((double)(2*p) + 0.4*32.0) / (1.4*32.0);
    double power = (t - half) / 64.0;
    double sc = pow(sbase, power);
    g_cos[idx] = (float)cos(f);
    g_sin[idx] = (float)sin(f);
    g_xs [idx] = (float)sc;
}

// ============================================================
// Kernel 2: TF32 GEMM, 128x128 tile, 8 warps (2x4), warp 64x32
//   QKV=true : C = X*W+b scattered to g_qkv[which][B][H][N][D]
//   QKV=false: C = g_att*W+b -> out
// ============================================================
template<int NC, bool QKV>
__global__ __launch_bounds__(256) void gemm_tf32_kernel(
    const float* __restrict__ X, const float* __restrict__ W,
    const float* __restrict__ bias, float* __restrict__ out)
{
    __shared__ unsigned As[128*36];   // [m][k], stride 36 (conflict-free frags)
    __shared__ unsigned Bs[32*136];   // [k][n], stride 136

    const float* Xp = QKV ? X : (const float*)g_att;

    int tid = threadIdx.x;
    int lane = tid & 31, warp = tid >> 5;
    int lq = lane >> 2, lr = lane & 3;
    int wm = (warp >> 2) * 64;
    int wn = (warp & 3) * 32;
    int bm = blockIdx.y * 128, bn = blockIdx.x * 128;

    float acc[4][4][4];
#pragma unroll
    for (int mi = 0; mi < 4; mi++)
#pragma unroll
        for (int ni = 0; ni < 4; ni++)
#pragma unroll
            for (int r = 0; r < 4; r++) acc[mi][ni][r] = 0.f;

    int ar = tid >> 3, ac = (tid & 7) << 2;     // A: 4 passes of 32 rows
    int br = tid >> 5, bc = (tid & 31) << 2;    // B: 4 passes of 8 k-rows

    for (int k0 = 0; k0 < 1024; k0 += 32) {
        float4 av[4], bv[4];
#pragma unroll
        for (int p = 0; p < 4; p++)
            av[p] = *(const float4*)(Xp + (size_t)(bm + ar + p*32)*1024 + k0 + ac);
#pragma unroll
        for (int p = 0; p < 4; p++)
            bv[p] = *(const float4*)(W + (size_t)(k0 + br + p*8)*NC + bn + bc);
        __syncthreads();
#pragma unroll
        for (int p = 0; p < 4; p++) {
            unsigned* d = &As[(ar + p*32)*36 + ac];
            d[0]=f2tf(av[p].x); d[1]=f2tf(av[p].y); d[2]=f2tf(av[p].z); d[3]=f2tf(av[p].w);
            unsigned* e = &Bs[(br + p*8)*136 + bc];
            e[0]=f2tf(bv[p].x); e[1]=f2tf(bv[p].y); e[2]=f2tf(bv[p].z); e[3]=f2tf(bv[p].w);
        }
        __syncthreads();
#pragma unroll
        for (int kk = 0; kk < 4; kk++) {
            unsigned af[4][4], bf[4][2];
#pragma unroll
            for (int mi = 0; mi < 4; mi++) {
                int r = wm + mi*16 + lq, c = kk*8 + lr;
                af[mi][0] = As[r*36 + c];
                af[mi][1] = As[(r+8)*36 + c];
                af[mi][2] = As[r*36 + c + 4];
                af[mi][3] = As[(r+8)*36 + c + 4];
            }
#pragma unroll
            for (int ni = 0; ni < 4; ni++) {
                int c = wn + ni*8 + lq, r = kk*8 + lr;
                bf[ni][0] = Bs[r*136 + c];
                bf[ni][1] = Bs[(r+4)*136 + c];
            }
#pragma unroll
            for (int mi = 0; mi < 4; mi++)
#pragma unroll
                for (int ni = 0; ni < 4; ni++)
                    mma8(acc[mi][ni], af[mi], bf[ni]);
        }
    }

    // epilogue
#pragma unroll
    for (int mi = 0; mi < 4; mi++) {
#pragma unroll
        for (int ni = 0; ni < 4; ni++) {
            int col = bn + wn + ni*8 + 2*lr;
            float bz0 = bias[col], bz1 = bias[col+1];
            int rA = bm + wm + mi*16 + lq;
            int rB = rA + 8;
            float2 vA = make_float2(acc[mi][ni][0] + bz0, acc[mi][ni][1] + bz1);
            float2 vB = make_float2(acc[mi][ni][2] + bz0, acc[mi][ni][3] + bz1);
            if (QKV) {
                int which = col >> 10, hh = (col >> 6) & 15, dd = col & 63;
                int bA = rA >> 11, nA = rA & 2047;
                int bB = rB >> 11, nB = rB & 2047;
                *(float2*)&g_qkv[((size_t)(((which*2 + bA)*16 + hh))*2048 + nA)*64 + dd] = vA;
                *(float2*)&g_qkv[((size_t)(((which*2 + bB)*16 + hh))*2048 + nB)*64 + dd] = vB;
            } else {
                *(float2*)&out[(size_t)rA*NC + col] = vA;
                *(float2*)&out[(size_t)rB*NC + col] = vB;
            }
        }
    }
}

// ============================================================
// Kernel 3: RoPE apply (q * xs, k / xs)
// ============================================================
__global__ void rope_apply_kernel() {
    int idx = blockIdx.x * blockDim.x + threadIdx.x;
    int pr = idx & 31;
    int n  = (idx >> 5)  & 2047;
    int h  = (idx >> 16) & 15;
    int b  = (idx >> 20) & 1;
    int w  = (idx >> 21) & 1;
    size_t base = ((size_t)((w*BATCH+b)*NHEADS + h)*NTOK + n)*HDIM + (pr << 1);
    float x0 = g_qkv[base], x1 = g_qkv[base+1];
    int ti = (n << 6) + (pr << 1);
    float c = g_cos[ti], s = g_sin[ti], xs = g_xs[ti];
    float y0 = x0*c - x1*s;
    float y1 = x1*c + x0*s;
    if (w == 0) { y0 *= xs; y1 *= xs; }
    else        { y0 /= xs; y1 /= xs; }
    g_qkv[base]   = y0;
    g_qkv[base+1] = y1;
}

// ============================================================
// Kernel 4: flash attention with TF32 mma
//   grid (16, 32), 256 thr (8 warps). Warp owns 16 q-rows.
//   Q frags in regs; K,V,P tiles in smem (stride 72, conflict-free).
// ============================================================
#define FSTR 72
#define FLASH_SMEM (256*FSTR*4)   // Ks(64) + Vs(64) + Ps(128) rows

__global__ __launch_bounds__(256, 1) void flash_tf32_kernel() {
    extern __shared__ unsigned sm_u[];
    unsigned* Ks = sm_u;                 // [64][FSTR]  tf32 bits of K (token x d)
    unsigned* Vs = sm_u + 64*FSTR;       // [64][FSTR]  tf32 bits of V (token x d)
    unsigned* Ps = sm_u + 128*FSTR;      // [128][FSTR] Q staging, then P

    int tid = threadIdx.x;
    int lane = tid & 31, warp = tid >> 5;
    int lq = lane >> 2, lr = lane & 3;
    int qt = blockIdx.x, bh = blockIdx.y;
    int b = bh >> 4, h = bh & 15;
    int r0 = warp * 16;

    const float* Qg = g_qkv + ((size_t)((0*BATCH + b)*NHEADS + h))*NTOK*HDIM + (size_t)qt*128*HDIM;
    const float* Kg = g_qkv + ((size_t)((1*BATCH + b)*NHEADS + h))*NTOK*HDIM;
    const float* Vg = g_qkv + ((size_t)((2*BATCH + b)*NHEADS + h))*NTOK*HDIM;

    // stage Q (scaled by 1/8, tf32) into Ps, then frag-load to regs
    {
        int r = tid >> 4, c4 = (tid & 15) << 2;
#pragma unroll
        for (int p = 0; p < 8; p++) {
            float4 v = *(const float4*)(Qg + (size_t)(r + p*16)*HDIM + c4);
            unsigned* d = &Ps[(r + p*16)*FSTR + c4];
            d[0] = f2tf(v.x*0.125f); d[1] = f2tf(v.y*0.125f);
            d[2] = f2tf(v.z*0.125f); d[3] = f2tf(v.w*0.125f);
        }
    }
    __syncthreads();

    unsigned qf[8][4];
#pragma unroll
    for (int kk = 0; kk < 8; kk++) {
        int c = kk*8 + lr;
        qf[kk][0] = Ps[(r0 + lq)*FSTR + c];
        qf[kk][1] = Ps[(r0 + lq + 8)*FSTR + c];
        qf[kk][2] = Ps[(r0 + lq)*FSTR + c + 4];
        qf[kk][3] = Ps[(r0 + lq + 8)*FSTR + c + 4];
    }

    float O[8][4];
    float mstate[2] = {-1e30f, -1e30f};
    float lstate[2] = {0.f, 0.f};
#pragma unroll
    for (int n = 0; n < 8; n++)
#pragma unroll
        for (int r = 0; r < 4; r++) O[n][r] = 0.f;

    for (int kt = 0; kt < NTOK/64; kt++) {
        __syncthreads();   // WAR on Ks/Vs/Ps from previous iter
        {
            int r = tid >> 4, c4 = (tid & 15) << 2;
            const float* kg = Kg + (size_t)kt*64*HDIM;
            const float* vg = Vg + (size_t)kt*64*HDIM;
#pragma unroll
            for (int p = 0; p < 4; p++) {
                float4 kv = *(const float4*)(kg + (size_t)(r + p*16)*HDIM + c4);
                unsigned* dk = &Ks[(r + p*16)*FSTR + c4];
                dk[0]=f2tf(kv.x); dk[1]=f2tf(kv.y); dk[2]=f2tf(kv.z); dk[3]=f2tf(kv.w);
                float4 vv = *(const float4*)(vg + (size_t)(r + p*16)*HDIM + c4);
                unsigned* dv = &Vs[(r + p*16)*FSTR + c4];
                dv[0]=f2tf(vv.x); dv[1]=f2tf(vv.y); dv[2]=f2tf(vv.z); dv[3]=f2tf(vv.w);
            }
        }
        __syncthreads();

        // ---- S = Q K^T : 8 n-tiles of 8 tokens ----
        float s[8][4];
#pragma unroll
        for (int n = 0; n < 8; n++) {
            s[n][0] = s[n][1] = s[n][2] = s[n][3] = 0.f;
#pragma unroll
            for (int kk = 0; kk < 8; kk++) {
                unsigned kb[2];
                int row = (n*8 + lq)*FSTR + kk*8 + lr;
                kb[0] = Ks[row];
                kb[1] = Ks[row + 4];
                mma8(s[n], qf[kk], kb);
            }
        }

        // ---- online softmax (rows lq and lq+8, quad-reduce over lr) ----
        float mA = -1e30f, mB = -1e30f;
#pragma unroll
        for (int n = 0; n < 8; n++) {
            mA = fmaxf(mA, fmaxf(s[n][0], s[n][1]));
            mB = fmaxf(mB, fmaxf(s[n][2], s[n][3]));
        }
        mA = fmaxf(mA, __shfl_xor_sync(0xffffffffu, mA, 1));
        mA = fmaxf(mA, __shfl_xor_sync(0xffffffffu, mA, 2));
        mB = fmaxf(mB, __shfl_xor_sync(0xffffffffu, mB, 1));
        mB = fmaxf(mB, __shfl_xor_sync(0xffffffffu, mB, 2));
        float mnA = fmaxf(mstate[0], mA), mnB = fmaxf(mstate[1], mB);
        float corrA = __expf(mstate[0] - mnA), corrB = __expf(mstate[1] - mnB);
        float sumA = 0.f, sumB = 0.f;
#pragma unroll
        for (int n = 0; n < 8; n++) {
            float p0 = __expf(s[n][0] - mnA), p1 = __expf(s[n][1] - mnA);
            float p2 = __expf(s[n][2] - mnB), p3 = __expf(s[n][3] - mnB);
            sumA += p0 + p1; sumB += p2 + p3;
            uint2 uA; uA.x = f2tf(p0); uA.y = f2tf(p1);
            uint2 uB; uB.x = f2tf(p2); uB.y = f2tf(p3);
            *(uint2*)&Ps[(r0 + lq)*FSTR + n*8 + 2*lr]     = uA;
            *(uint2*)&Ps[(r0 + lq + 8)*FSTR + n*8 + 2*lr] = uB;
        }
        sumA += __shfl_xor_sync(0xffffffffu, sumA, 1);
        sumA += __shfl_xor_sync(0xffffffffu, sumA, 2);
        sumB += __shfl_xor_sync(0xffffffffu, sumB, 1);
        sumB += __shfl_xor_sync(0xffffffffu, sumB, 2);
        lstate[0] = lstate[0]*corrA + sumA; mstate[0] = mnA;
        lstate[1] = lstate[1]*corrB + sumB; mstate[1] = mnB;
#pragma unroll
        for (int n = 0; n < 8; n++) {
            O[n][0] *= corrA; O[n][1] *= corrA;
            O[n][2] *= corrB; O[n][3] *= corrB;
        }
        __syncwarp();   // P visible to warp before frag reload

        // ---- O += P V ----
#pragma unroll
        for (int kk = 0; kk < 8; kk++) {
            unsigned pa[4];
            int c = kk*8 + lr;
            pa[0] = Ps[(r0 + lq)*FSTR + c];
            pa[1] = Ps[(r0 + lq + 8)*FSTR + c];
            pa[2] = Ps[(r0 + lq)*FSTR + c + 4];
            pa[3] = Ps[(r0 + lq + 8)*FSTR + c + 4];
#pragma unroll
            for (int n = 0; n < 8; n++) {
                unsigned vb[2];
                vb[0] = Vs[(kk*8 + lr)*FSTR + n*8 + lq];
                vb[1] = Vs[(kk*8 + lr + 4)*FSTR + n*8 + lq];
                mma8(O[n], pa, vb);
            }
        }
    }

    // epilogue: normalize, write [B][N][H*D]
    float invA = 1.f / lstate[0], invB = 1.f / lstate[1];
    int rowA = qt*128 + r0 + lq;
    int rowB = rowA + 8;
#pragma unroll
    for (int n = 0; n < 8; n++) {
        int col = h*HDIM + n*8 + 2*lr;
        float2 vA = make_float2(O[n][0]*invA, O[n][1]*invA);
        float2 vB = make_float2(O[n][2]*invB, O[n][3]*invB);
        *(float2*)&g_att[(size_t)(b*NTOK + rowA)*D_MODEL + col] = vA;
        *(float2*)&g_att[(size_t)(b*NTOK + rowB)*D_MODEL + col] = vB;
    }
}

// ============================================================
// launch
// ============================================================
extern "C" void kernel_launch(void* const* d_in, const int* in_sizes, int n_in,
                              void* d_out, int out_size) {
    const float* x      = (const float*)d_in[0];
    const float* w_qkv  = (const float*)d_in[1];
    const float* b_qkv  = (const float*)d_in[2];
    const float* w_proj = (const float*)d_in[3];
    const float* b_proj = (const float*)d_in[4];
    float* out = (float*)d_out;
    (void)in_sizes; (void)n_in; (void)out_size;

    rope_tables_kernel<<<(NTOK*HDIM)/256, 256>>>();
    gemm_tf32_kernel<QKVCOLS, true><<<dim3(QKVCOLS/128, MROWS/128), 256>>>(x, w_qkv, b_qkv, nullptr);
    rope_apply_kernel<<<(2*BATCH*NHEADS*NTOK*(HDIM/2))/256, 256>>>();
    cudaFuncSetAttribute(flash_tf32_kernel, cudaFuncAttributeMaxDynamicSharedMemorySize, FLASH_SMEM);
    flash_tf32_kernel<<<dim3(NTOK/128, BATCH*NHEADS), 256, FLASH_SMEM>>>();
    gemm_tf32_kernel<D_MODEL, false><<<dim3(D_MODEL/128, MROWS/128), 256>>>(nullptr, w_proj, b_proj, out);
}